// round 16
// baseline (speedup 1.0000x reference)
#include <cuda_runtime.h>
#include <cuda_bf16.h>
#include <cstdint>

#define TT 512
#define BB 128
#define KK 20
#define VV 10002
#define PPY 500

#define HS 260    // hs row stride (u32)
#define GSB 132   // g_s batch-row stride (floats)

// ---- static device scratch ----
__device__ float g_Pc[(size_t)VV * 2048];
__device__ float g_Pp[(size_t)PPY * 2048];
__device__ float g_Pt[(size_t)KK * 2048];
__device__ float g_h2[(size_t)TT * BB * 512];
__device__ float g_em[(size_t)TT * BB * KK];
__device__ float g_res[BB];
__device__ uint32_t g_stg[16 * 2 * 16 * 256];   // [dirgrp16][parity][batch16][h256] tf32
__device__ unsigned int g_flag[2 * 8 * 8 * 32]; // [dir][bi][ui] padded 128B

__device__ __forceinline__ float tanha(float x) {
    float y; asm("tanh.approx.f32 %0, %1;" : "=f"(y) : "f"(x)); return y;
}
__device__ __forceinline__ float sigm(float x) { return 0.5f * tanha(0.5f * x) + 0.5f; }
__device__ __forceinline__ unsigned long long splat2(float w) {
    unsigned long long r; asm("mov.b64 %0, {%1, %1};" : "=l"(r) : "f"(w)); return r;
}
__device__ __forceinline__ void fma2(unsigned long long& a, unsigned long long m, unsigned long long w) {
    asm("fma.rn.f32x2 %0, %1, %2, %0;" : "+l"(a) : "l"(m), "l"(w));
}
__device__ __forceinline__ void unpk(unsigned long long v, float& x, float& y) {
    asm("mov.b64 {%0, %1}, %2;" : "=f"(x), "=f"(y) : "l"(v));
}
__device__ __forceinline__ uint32_t f2tf(float f) {
    uint32_t u; asm("cvt.rna.tf32.f32 %0, %1;" : "=r"(u) : "f"(f)); return u;
}
__device__ __forceinline__ void mma_tf32(float* c,
    uint32_t a0, uint32_t a1, uint32_t a2, uint32_t a3, uint32_t b0, uint32_t b1)
{
    asm("mma.sync.aligned.m16n8k8.row.col.f32.tf32.tf32.f32 "
        "{%0,%1,%2,%3}, {%4,%5,%6,%7}, {%8,%9}, {%0,%1,%2,%3};"
        : "+f"(c[0]), "+f"(c[1]), "+f"(c[2]), "+f"(c[3])
        : "r"(a0), "r"(a1), "r"(a2), "r"(a3), "r"(b0), "r"(b1));
}

__global__ void bc_init_kernel() {
    if (threadIdx.x < 128) g_flag[threadIdx.x * 32] = 0u;
}

// ---- shared GEMM tile routine ----
__device__ __forceinline__ void gemm_tile(
    const float* __restrict__ A, int Ne, int De, int doff,
    const float* __restrict__ W, float* __restrict__ P,
    int rb, int cb, int dir)
{
    __shared__ float As[10][132];
    __shared__ float Bs[10][132];
    int tid = threadIdx.x, tx = tid & 15, ty = tid >> 4;
    unsigned long long acc2[8][4];
#pragma unroll
    for (int i = 0; i < 8; ++i)
#pragma unroll
        for (int j = 0; j < 4; ++j) acc2[i][j] = 0ull;

    for (int k0 = 0; k0 < De; k0 += 10) {
#pragma unroll
        for (int i = 0; i < 5; ++i) {
            int idx = tid + i * 256, kc = idx >> 7, r = idx & 127;
            int rg = rb + r;
            As[kc][r] = (rg < Ne) ? A[(size_t)rg * De + k0 + kc] : 0.f;
        }
#pragma unroll
        for (int i = 0; i < 5; ++i) {
            int idx = tid + i * 256, kc = idx >> 7, c = idx & 127;
            Bs[kc][c] = W[(size_t)(cb + c) * 450 + doff + k0 + kc];
        }
        __syncthreads();
#pragma unroll
        for (int k = 0; k < 10; ++k) {
            float4 a0 = *reinterpret_cast<const float4*>(&As[k][tx * 4]);
            float4 a1 = *reinterpret_cast<const float4*>(&As[k][tx * 4 + 64]);
            ulonglong2 b01 = *reinterpret_cast<const ulonglong2*>(&Bs[k][ty * 4]);
            ulonglong2 b23 = *reinterpret_cast<const ulonglong2*>(&Bs[k][ty * 4 + 64]);
            float av[8] = {a0.x, a0.y, a0.z, a0.w, a1.x, a1.y, a1.z, a1.w};
#pragma unroll
            for (int i = 0; i < 8; ++i) {
                unsigned long long a2 = splat2(av[i]);
                fma2(acc2[i][0], b01.x, a2);
                fma2(acc2[i][1], b01.y, a2);
                fma2(acc2[i][2], b23.x, a2);
                fma2(acc2[i][3], b23.y, a2);
            }
        }
        __syncthreads();
    }
#pragma unroll
    for (int i = 0; i < 8; ++i) {
        int r = (i < 4) ? (tx * 4 + i) : (64 + tx * 4 + (i - 4));
        int rg = rb + r;
        if (rg >= Ne) continue;
        float o[8];
        unpk(acc2[i][0], o[0], o[1]);
        unpk(acc2[i][1], o[2], o[3]);
        unpk(acc2[i][2], o[4], o[5]);
        unpk(acc2[i][3], o[6], o[7]);
        float* dst = P + (size_t)rg * 2048 + (size_t)dir * 1024 + cb;
        *reinterpret_cast<float4*>(&dst[ty * 4]) = make_float4(o[0], o[1], o[2], o[3]);
        *reinterpret_cast<float4*>(&dst[ty * 4 + 64]) = make_float4(o[4], o[5], o[6], o[7]);
    }
}

__global__ void __launch_bounds__(256) gemm_c_kernel(
    const float* __restrict__ A, const float* __restrict__ wf, const float* __restrict__ wb)
{
    int dir = blockIdx.z;
    gemm_tile(A, VV, 300, 0, dir ? wb : wf, g_Pc, blockIdx.x * 128, blockIdx.y * 128, dir);
}

__global__ void __launch_bounds__(256) gemm_pt_kernel(
    const float* __restrict__ Ap, const float* __restrict__ At,
    const float* __restrict__ wf, const float* __restrict__ wb)
{
    int dir = blockIdx.z;
    const float* W = dir ? wb : wf;
    if (blockIdx.x < 4)
        gemm_tile(Ap, PPY, 100, 300, W, g_Pp, blockIdx.x * 128, blockIdx.y * 128, dir);
    else
        gemm_tile(At, KK, 50, 400, W, g_Pt, 0, blockIdx.y * 128, dir);
}

// persistent BiLSTM: 64 CTAs = batch-tile(8 of 16) x unit-tile(8 of 32).
// Each CTA runs BOTH directions alternately per super-step: each dir's
// flag round trip hides under the other dir's compute.
// Fwd A-fragments in registers; bwd A-fragments in smem [kk][j][tid].
#define SMEM_U32 (256 * 128 + 2 * 16 * HS + 16 * GSB)

__global__ void __launch_bounds__(256, 1) lstm_kernel(
    const int* __restrict__ xi, const int* __restrict__ pin, const int* __restrict__ ptag,
    const float* __restrict__ whh_f, const float* __restrict__ whh_b,
    const float* __restrict__ bihf, const float* __restrict__ bhhf,
    const float* __restrict__ bihb, const float* __restrict__ bhhb)
{
    extern __shared__ uint32_t smu[];
    uint32_t* wsm = smu;                         // [128-chunks][j][tid] bwd A frags
    uint32_t* hs0 = smu + 256 * 128;             // [16][HS] fwd h (tf32)
    uint32_t* hs1 = hs0 + 16 * HS;               // [16][HS] bwd h (tf32)
    float*    g_s = reinterpret_cast<float*>(hs1 + 16 * HS);  // [16][GSB]

    int tid = threadIdx.x, bx = blockIdx.x;
    int bi = bx >> 3, ui = bx & 7;

    for (int i = tid; i < 2 * 16 * HS; i += 256) hs0[i] = 0u;

    // identities
    int lane = tid & 31, wp = tid >> 5;
    int gID = lane >> 2, ac = lane & 3;
    int ar = wp * 16 + gID;
    int p2_b = tid >> 5, p2_j = tid & 31;
    int u_g = ui * 32 + p2_j;
    int rb_b = tid >> 4, rcc = tid & 15;
    int rl_h0 = rcc * 16;
    bool own_chunk = ((rcc >> 1) == ui);

    // fwd A fragments in registers; bwd A fragments to smem
    uint32_t wA[128];
    {
        int rA = ar, rB = ar + 8;
        int GA = ((rA & 3) << 8) + ui * 32 + (rA >> 2);
        int GB = ((rB & 3) << 8) + ui * 32 + (rB >> 2);
        const float* fA = whh_f + (size_t)GA * 256;
        const float* fB = whh_f + (size_t)GB * 256;
        const float* bA = whh_b + (size_t)GA * 256;
        const float* bB = whh_b + (size_t)GB * 256;
#pragma unroll
        for (int kk = 0; kk < 32; ++kk) {
            int k = kk * 8;
            wA[4 * kk + 0] = f2tf(fA[k + ac]);
            wA[4 * kk + 1] = f2tf(fB[k + ac]);
            wA[4 * kk + 2] = f2tf(fA[k + ac + 4]);
            wA[4 * kk + 3] = f2tf(fB[k + ac + 4]);
            wsm[(kk * 4 + 0) * 256 + tid] = f2tf(bA[k + ac]);
            wsm[(kk * 4 + 1) * 256 + tid] = f2tf(bB[k + ac]);
            wsm[(kk * 4 + 2) * 256 + tid] = f2tf(bA[k + ac + 4]);
            wsm[(kk * 4 + 3) * 256 + tid] = f2tf(bB[k + ac + 4]);
        }
    }

    float bias0[4], bias1[4];
#pragma unroll
    for (int g = 0; g < 4; ++g) {
        int G = (g << 8) + u_g;
        bias0[g] = bihf[G] + bhhf[G];
        bias1[g] = bihb[G] + bhhb[G];
    }
    __syncthreads();

    float c0a = 0.f, c0b = 0.f, c1a = 0.f, c1b = 0.f;  // cell states fwd/bwd x 2 cells
    unsigned int* myf0 = g_flag + ((0 * 8 + bi) * 8 + ui) * 32;
    unsigned int* myf1 = g_flag + ((1 * 8 + bi) * 8 + ui) * 32;
    unsigned int* rdf0 = g_flag + ((0 * 8 + bi) * 8 + (rcc >> 1)) * 32;
    unsigned int* rdf1 = g_flag + ((1 * 8 + bi) * 8 + (rcc >> 1)) * 32;
    uint32_t* stg0 = g_stg + (size_t)(0 * 8 + bi) * 2 * 16 * 256;
    uint32_t* stg1 = g_stg + (size_t)(1 * 8 + bi) * 2 * 16 * 256;
    int bg0 = bi * 16 + p2_b;
    int bg1 = bg0 + 8;

    for (int s = 0; s < TT; ++s) {
        int t0 = s;
        int t1 = TT - 1 - s;

        // ---- prefetch both dirs' phase-2 inputs ----
        float pre0[2][4], pre1[2][4];
#pragma unroll
        for (int d = 0; d < 2; ++d) {
            int t = d ? t1 : t0;
            int dof = d * 1024;
            int xv0 = xi[bg0 * TT + t], pv0 = pin[bg0 * TT + t], tv0 = ptag[bg0 * TT + t];
            int xv1 = xi[bg1 * TT + t], pv1 = pin[bg1 * TT + t], tv1 = ptag[bg1 * TT + t];
            const float* pc0 = g_Pc + (size_t)xv0 * 2048 + dof + u_g;
            const float* pp0 = g_Pp + (size_t)pv0 * 2048 + dof + u_g;
            const float* pt0 = g_Pt + (size_t)tv0 * 2048 + dof + u_g;
            const float* pc1 = g_Pc + (size_t)xv1 * 2048 + dof + u_g;
            const float* pp1 = g_Pp + (size_t)pv1 * 2048 + dof + u_g;
            const float* pt1 = g_Pt + (size_t)tv1 * 2048 + dof + u_g;
            float* pr0 = d ? pre1[0] : pre0[0];
            float* pr1 = d ? pre1[1] : pre0[1];
            const float* bs = d ? bias1 : bias0;
#pragma unroll
            for (int g = 0; g < 4; ++g) {
                pr0[g] = bs[g] + pc0[g * 256] + pp0[g * 256] + pt0[g * 256];
                pr1[g] = bs[g] + pc1[g * 256] + pp1[g * 256] + pt1[g * 256];
            }
        }

        // ================= direction 0 (forward) =================
        if (s > 0) {
            if (!own_chunk) {
                unsigned v, target = (unsigned)s;
                do {
                    asm volatile("ld.acquire.gpu.u32 %0, [%1];" : "=r"(v) : "l"(rdf0) : "memory");
                } while (v < target);
                const uint32_t* src = stg0 + (size_t)(((s - 1) & 1) * 16 + rb_b) * 256 + rl_h0;
                uint32_t* dst = hs0 + rb_b * HS + rl_h0;
#pragma unroll
                for (int q = 0; q < 4; ++q)
                    *reinterpret_cast<uint4*>(dst + q * 4) =
                        *reinterpret_cast<const uint4*>(src + q * 4);
            }
            __syncthreads();
        }
        {
            float cA[4] = {0.f, 0.f, 0.f, 0.f};
            float cB[4] = {0.f, 0.f, 0.f, 0.f};
            const uint32_t* hb0 = hs0 + gID * HS;
            const uint32_t* hb1 = hs0 + (gID + 8) * HS;
#pragma unroll
            for (int kk = 0; kk < 32; ++kk) {
                int k = kk * 8;
                uint32_t b0 = hb0[k + ac];
                uint32_t b1 = hb0[k + ac + 4];
                uint32_t b2 = hb1[k + ac];
                uint32_t b3 = hb1[k + ac + 4];
                mma_tf32(cA, wA[4 * kk], wA[4 * kk + 1], wA[4 * kk + 2], wA[4 * kk + 3], b0, b1);
                mma_tf32(cB, wA[4 * kk], wA[4 * kk + 1], wA[4 * kk + 2], wA[4 * kk + 3], b2, b3);
            }
            int bc = 2 * ac;
            g_s[bc * GSB + ar]           = cA[0];
            g_s[(bc + 1) * GSB + ar]     = cA[1];
            g_s[bc * GSB + ar + 8]       = cA[2];
            g_s[(bc + 1) * GSB + ar + 8] = cA[3];
            g_s[(bc + 8) * GSB + ar]     = cB[0];
            g_s[(bc + 9) * GSB + ar]     = cB[1];
            g_s[(bc + 8) * GSB + ar + 8] = cB[2];
            g_s[(bc + 9) * GSB + ar + 8] = cB[3];
        }
        __syncthreads();
        {
            uint32_t* stg_w = stg0 + (size_t)(s & 1) * 16 * 256;
#pragma unroll
            for (int cc = 0; cc < 2; ++cc) {
                int bl = p2_b + cc * 8;
                int bg = cc ? bg1 : bg0;
                float4 gv = *reinterpret_cast<const float4*>(&g_s[bl * GSB + p2_j * 4]);
                float ig = sigm(pre0[cc][0] + gv.x);
                float fg = sigm(pre0[cc][1] + gv.y);
                float gg = tanha(pre0[cc][2] + gv.z);
                float og = sigm(pre0[cc][3] + gv.w);
                float c = cc ? c0b : c0a;
                c = fg * c + ig * gg;
                if (cc) c0b = c; else c0a = c;
                float hv = og * tanha(c);
                uint32_t htf = f2tf(hv);
                stg_w[bl * 256 + u_g] = htf;
                g_h2[((size_t)(t0 * BB + bg)) * 512 + u_g] = hv;
                hs0[bl * HS + u_g] = htf;
            }
        }
        __syncthreads();
        if (tid == 0)
            asm volatile("st.release.gpu.global.u32 [%0], %1;"
                         :: "l"(myf0), "r"((unsigned)(s + 1)) : "memory");

        // ================= direction 1 (backward) =================
        if (s > 0) {
            if (!own_chunk) {
                unsigned v, target = (unsigned)s;
                do {
                    asm volatile("ld.acquire.gpu.u32 %0, [%1];" : "=r"(v) : "l"(rdf1) : "memory");
                } while (v < target);
                const uint32_t* src = stg1 + (size_t)(((s - 1) & 1) * 16 + rb_b) * 256 + rl_h0;
                uint32_t* dst = hs1 + rb_b * HS + rl_h0;
#pragma unroll
                for (int q = 0; q < 4; ++q)
                    *reinterpret_cast<uint4*>(dst + q * 4) =
                        *reinterpret_cast<const uint4*>(src + q * 4);
            }
            __syncthreads();
        }
        {
            float cA[4] = {0.f, 0.f, 0.f, 0.f};
            float cB[4] = {0.f, 0.f, 0.f, 0.f};
            const uint32_t* hb0 = hs1 + gID * HS;
            const uint32_t* hb1 = hs1 + (gID + 8) * HS;
#pragma unroll
            for (int kk = 0; kk < 32; ++kk) {
                int k = kk * 8;
                uint32_t a0 = wsm[(kk * 4 + 0) * 256 + tid];
                uint32_t a1 = wsm[(kk * 4 + 1) * 256 + tid];
                uint32_t a2 = wsm[(kk * 4 + 2) * 256 + tid];
                uint32_t a3 = wsm[(kk * 4 + 3) * 256 + tid];
                uint32_t b0 = hb0[k + ac];
                uint32_t b1 = hb0[k + ac + 4];
                uint32_t b2 = hb1[k + ac];
                uint32_t b3 = hb1[k + ac + 4];
                mma_tf32(cA, a0, a1, a2, a3, b0, b1);
                mma_tf32(cB, a0, a1, a2, a3, b2, b3);
            }
            int bc = 2 * ac;
            g_s[bc * GSB + ar]           = cA[0];
            g_s[(bc + 1) * GSB + ar]     = cA[1];
            g_s[bc * GSB + ar + 8]       = cA[2];
            g_s[(bc + 1) * GSB + ar + 8] = cA[3];
            g_s[(bc + 8) * GSB + ar]     = cB[0];
            g_s[(bc + 9) * GSB + ar]     = cB[1];
            g_s[(bc + 8) * GSB + ar + 8] = cB[2];
            g_s[(bc + 9) * GSB + ar + 8] = cB[3];
        }
        __syncthreads();
        {
            uint32_t* stg_w = stg1 + (size_t)(s & 1) * 16 * 256;
#pragma unroll
            for (int cc = 0; cc < 2; ++cc) {
                int bl = p2_b + cc * 8;
                int bg = cc ? bg1 : bg0;
                float4 gv = *reinterpret_cast<const float4*>(&g_s[bl * GSB + p2_j * 4]);
                float ig = sigm(pre1[cc][0] + gv.x);
                float fg = sigm(pre1[cc][1] + gv.y);
                float gg = tanha(pre1[cc][2] + gv.z);
                float og = sigm(pre1[cc][3] + gv.w);
                float c = cc ? c1b : c1a;
                c = fg * c + ig * gg;
                if (cc) c1b = c; else c1a = c;
                float hv = og * tanha(c);
                uint32_t htf = f2tf(hv);
                stg_w[bl * 256 + u_g] = htf;
                g_h2[((size_t)(t1 * BB + bg)) * 512 + 256 + u_g] = hv;
                hs1[bl * HS + u_g] = htf;
            }
        }
        __syncthreads();
        if (tid == 0)
            asm volatile("st.release.gpu.global.u32 [%0], %1;"
                         :: "l"(myf1), "r"((unsigned)(s + 1)) : "memory");
    }
}

// emissions: w_out staged in smem, 64 (t,b) pairs per block
__global__ void __launch_bounds__(256) emis_kernel(
    const float* __restrict__ wout, const float* __restrict__ bout)
{
    __shared__ float ws[KK][520];
    __shared__ float bs[KK];
    int tid = threadIdx.x;
    for (int idx = tid; idx < KK * 512; idx += 256) {
        int k = idx >> 9, c = idx & 511;
        ws[k][c] = wout[idx];
    }
    if (tid < KK) bs[tid] = bout[tid];
    __syncthreads();

    int warp = tid >> 5, lane = tid & 31;
#pragma unroll
    for (int it = 0; it < 8; ++it) {
        int p = blockIdx.x * 64 + it * 8 + warp;   // t*128+b
        const float* hr = g_h2 + (size_t)p * 512;
        float4 h[4];
#pragma unroll
        for (int c = 0; c < 4; ++c)
            h[c] = *reinterpret_cast<const float4*>(&hr[c * 128 + lane * 4]);
        float* em = g_em + (size_t)p * KK;
        for (int k = 0; k < KK; ++k) {
            float s = 0.f;
#pragma unroll
            for (int c = 0; c < 4; ++c) {
                float4 w = *reinterpret_cast<const float4*>(&ws[k][c * 128 + lane * 4]);
                s = fmaf(h[c].x, w.x, s); s = fmaf(h[c].y, w.y, s);
                s = fmaf(h[c].z, w.z, s); s = fmaf(h[c].w, w.w, s);
            }
#pragma unroll
            for (int o = 16; o; o >>= 1) s += __shfl_xor_sync(0xffffffffu, s, o);
            if (lane == 0) em[k] = s + bs[k];
        }
    }
}

// CRF NLL per batch: warp per batch, lane = tag
__global__ void __launch_bounds__(32) crf_kernel(
    const int* __restrict__ y, const float* __restrict__ start,
    const float* __restrict__ endt, const float* __restrict__ trans)
{
    int b = blockIdx.x, lane = threadIdx.x;
    bool act = lane < KK;
    float trc[KK];
#pragma unroll
    for (int j = 0; j < KK; ++j) trc[j] = act ? trans[j * KK + lane] : 0.f;

    float alpha = act ? (start[lane] + g_em[(size_t)b * KK + lane]) : -1e30f;
    for (int t = 1; t < TT; ++t) {
        float e = act ? g_em[((size_t)t * BB + b) * KK + lane] : 0.f;
        float vj[KK], m = -1e30f;
#pragma unroll
        for (int j = 0; j < KK; ++j) {
            float aj = __shfl_sync(0xffffffffu, alpha, j);
            vj[j] = aj + trc[j];
            m = fmaxf(m, vj[j]);
        }
        float ssum = 0.f;
#pragma unroll
        for (int j = 0; j < KK; ++j) ssum += __expf(vj[j] - m);
        alpha = e + m + __logf(ssum);
    }
    float v = act ? (alpha + endt[lane]) : -1e30f;
    float m = v;
#pragma unroll
    for (int o = 16; o; o >>= 1) m = fmaxf(m, __shfl_xor_sync(0xffffffffu, m, o));
    float se = act ? __expf(v - m) : 0.f;
#pragma unroll
    for (int o = 16; o; o >>= 1) se += __shfl_xor_sync(0xffffffffu, se, o);
    float logZ = m + __logf(se);

    const int* yb = y + b * TT;
    float sc = 0.f;
    for (int t = 1 + lane; t < TT; t += 32) {
        int tp = yb[t - 1], tc = yb[t];
        sc += trans[tp * KK + tc] + g_em[((size_t)t * BB + b) * KK + tc];
    }
    if (lane == 0) {
        int t0 = yb[0];
        sc += start[t0] + g_em[(size_t)b * KK + t0] + endt[yb[TT - 1]];
    }
#pragma unroll
    for (int o = 16; o; o >>= 1) sc += __shfl_xor_sync(0xffffffffu, sc, o);
    if (lane == 0) g_res[b] = sc - logZ;
}

__global__ void __launch_bounds__(32) final_kernel(float* __restrict__ out) {
    int lane = threadIdx.x;
    float s = 0.f;
    for (int i = lane; i < BB; i += 32) s += g_res[i];
#pragma unroll
    for (int o = 16; o; o >>= 1) s += __shfl_xor_sync(0xffffffffu, s, o);
    if (lane == 0) out[0] = -s;
}

extern "C" void kernel_launch(void* const* d_in, const int* in_sizes, int n_in,
                              void* d_out, int out_size) {
    const int*   x_idx   = (const int*)d_in[0];
    const int*   y_tags  = (const int*)d_in[1];
    const int*   pretag  = (const int*)d_in[2];
    const int*   pinyin  = (const int*)d_in[3];
    const float* char_emb   = (const float*)d_in[5];
    const float* tag_emb    = (const float*)d_in[6];
    const float* pinyin_emb = (const float*)d_in[7];
    const float* wihf = (const float*)d_in[8];
    const float* whhf = (const float*)d_in[9];
    const float* bihf = (const float*)d_in[10];
    const float* bhhf = (const float*)d_in[11];
    const float* wihb = (const float*)d_in[12];
    const float* whhb = (const float*)d_in[13];
    const float* bihb = (const float*)d_in[14];
    const float* bhhb = (const float*)d_in[15];
    const float* wout  = (const float*)d_in[16];
    const float* bout  = (const float*)d_in[17];
    const float* start = (const float*)d_in[18];
    const float* endt  = (const float*)d_in[19];
    const float* trans = (const float*)d_in[20];
    float* out = (float*)d_out;

    cudaFuncSetAttribute(lstm_kernel,
                         cudaFuncAttributeMaxDynamicSharedMemorySize,
                         SMEM_U32 * (int)sizeof(uint32_t));

    bc_init_kernel<<<1, 128>>>();
    gemm_c_kernel<<<dim3(79, 8, 2), 256>>>(char_emb, wihf, wihb);
    gemm_pt_kernel<<<dim3(5, 8, 2), 256>>>(pinyin_emb, tag_emb, wihf, wihb);

    lstm_kernel<<<64, 256, SMEM_U32 * (int)sizeof(uint32_t)>>>(
        x_idx, pinyin, pretag, whhf, whhb, bihf, bhhf, bihb, bhhb);

    emis_kernel<<<(TT * BB) / 64, 256>>>(wout, bout);
    crf_kernel<<<BB, 32>>>(y_tags, start, endt, trans);
    final_kernel<<<1, 32>>>(out);
}

// round 17
// speedup vs baseline: 1.8017x; 1.8017x over previous
#include <cuda_runtime.h>
#include <cuda_bf16.h>
#include <cstdint>

#define TT 512
#define BB 128
#define KK 20
#define VV 10002
#define PPY 500

#define HS 260    // hs_s row stride (u32)
#define GS 21     // g_s row stride (floats)

// ---- static device scratch ----
__device__ float g_Pc[(size_t)VV * 2048];
__device__ float g_Pp[(size_t)PPY * 2048];
__device__ float g_Pt[(size_t)KK * 2048];
__device__ float g_h2[(size_t)TT * BB * 512];
__device__ float g_em[(size_t)TT * BB * KK];
__device__ float g_res[BB];
__device__ uint32_t g_stg[16 * 2 * 16 * 256];   // [group16][parity][batch16][h256] tf32
__device__ unsigned int g_bar[16 * 32];

__device__ __forceinline__ float tanha(float x) {
    float y; asm("tanh.approx.f32 %0, %1;" : "=f"(y) : "f"(x)); return y;
}
__device__ __forceinline__ float sigm(float x) { return 0.5f * tanha(0.5f * x) + 0.5f; }
__device__ __forceinline__ unsigned long long splat2(float w) {
    unsigned long long r; asm("mov.b64 %0, {%1, %1};" : "=l"(r) : "f"(w)); return r;
}
__device__ __forceinline__ void fma2(unsigned long long& a, unsigned long long m, unsigned long long w) {
    asm("fma.rn.f32x2 %0, %1, %2, %0;" : "+l"(a) : "l"(m), "l"(w));
}
__device__ __forceinline__ void unpk(unsigned long long v, float& x, float& y) {
    asm("mov.b64 {%0, %1}, %2;" : "=f"(x), "=f"(y) : "l"(v));
}
__device__ __forceinline__ uint32_t f2tf(float f) {
    uint32_t u; asm("cvt.rna.tf32.f32 %0, %1;" : "=r"(u) : "f"(f)); return u;
}
__device__ __forceinline__ void mma_tf32(float* c,
    uint32_t a0, uint32_t a1, uint32_t a2, uint32_t a3, uint32_t b0, uint32_t b1)
{
    asm("mma.sync.aligned.m16n8k8.row.col.f32.tf32.tf32.f32 "
        "{%0,%1,%2,%3}, {%4,%5,%6,%7}, {%8,%9}, {%0,%1,%2,%3};"
        : "+f"(c[0]), "+f"(c[1]), "+f"(c[2]), "+f"(c[3])
        : "r"(a0), "r"(a1), "r"(a2), "r"(a3), "r"(b0), "r"(b1));
}

__global__ void bc_init_kernel() {
    if (threadIdx.x < 16) g_bar[threadIdx.x * 32] = 0u;
}

// ---- tf32 mma GEMM for the char table: P[e][dir*1024+G] = A[e][:] . W[G][0:300]
__global__ void __launch_bounds__(256) gemm_c_mma_kernel(
    const float* __restrict__ A, const float* __restrict__ wf, const float* __restrict__ wb)
{
    __shared__ uint32_t Asm[128][36];
    __shared__ uint32_t Wsm[64][36];
    int dir = blockIdx.z;
    const float* W = dir ? wb : wf;
    int rb = blockIdx.x * 128;
    int cbN = blockIdx.y * 64;
    int tid = threadIdx.x, lane = tid & 31, wp = tid >> 5;
    int gID = lane >> 2, ac = lane & 3;
    int wm = wp & 3, wn = wp >> 2;
    int m0w = wm * 32, n0w = wn * 32;

    float acc[2][4][4];
#pragma unroll
    for (int i = 0; i < 2; ++i)
#pragma unroll
        for (int j = 0; j < 4; ++j)
#pragma unroll
            for (int q = 0; q < 4; ++q) acc[i][j][q] = 0.f;

    for (int k0 = 0; k0 < 300; k0 += 32) {
#pragma unroll
        for (int i = 0; i < 16; ++i) {
            int idx = tid + i * 256;
            int r = idx >> 5, c = idx & 31;
            int rg = rb + r, d = k0 + c;
            float v = (rg < VV && d < 300) ? A[(size_t)rg * 300 + d] : 0.f;
            Asm[r][c] = f2tf(v);
        }
#pragma unroll
        for (int i = 0; i < 8; ++i) {
            int idx = tid + i * 256;
            int n = idx >> 5, c = idx & 31;
            int d = k0 + c;
            float v = (d < 300) ? W[(size_t)(cbN + n) * 450 + d] : 0.f;
            Wsm[n][c] = f2tf(v);
        }
        __syncthreads();
#pragma unroll
        for (int kb = 0; kb < 32; kb += 8) {
            uint32_t a[2][4];
#pragma unroll
            for (int mt = 0; mt < 2; ++mt) {
                int mr = m0w + mt * 16 + gID;
                a[mt][0] = Asm[mr][kb + ac];
                a[mt][1] = Asm[mr + 8][kb + ac];
                a[mt][2] = Asm[mr][kb + ac + 4];
                a[mt][3] = Asm[mr + 8][kb + ac + 4];
            }
#pragma unroll
            for (int nt = 0; nt < 4; ++nt) {
                int nr = n0w + nt * 8 + gID;
                uint32_t b0 = Wsm[nr][kb + ac];
                uint32_t b1 = Wsm[nr][kb + ac + 4];
                mma_tf32(acc[0][nt], a[0][0], a[0][1], a[0][2], a[0][3], b0, b1);
                mma_tf32(acc[1][nt], a[1][0], a[1][1], a[1][2], a[1][3], b0, b1);
            }
        }
        __syncthreads();
    }
#pragma unroll
    for (int mt = 0; mt < 2; ++mt) {
#pragma unroll
        for (int half = 0; half < 2; ++half) {
            int mr = rb + m0w + mt * 16 + gID + half * 8;
            if (mr >= VV) continue;
            float* dst = g_Pc + (size_t)mr * 2048 + dir * 1024 + cbN;
#pragma unroll
            for (int nt = 0; nt < 4; ++nt) {
                float2 v;
                v.x = acc[mt][nt][half * 2];
                v.y = acc[mt][nt][half * 2 + 1];
                *reinterpret_cast<float2*>(&dst[n0w + nt * 8 + 2 * ac]) = v;
            }
        }
    }
}

// ---- FFMA2 GEMM tile (kept for the small pinyin/tag tables) ----
__device__ __forceinline__ void gemm_tile(
    const float* __restrict__ A, int Ne, int De, int doff,
    const float* __restrict__ W, float* __restrict__ P,
    int rb, int cb, int dir)
{
    __shared__ float As[10][132];
    __shared__ float Bs[10][132];
    int tid = threadIdx.x, tx = tid & 15, ty = tid >> 4;
    unsigned long long acc2[8][4];
#pragma unroll
    for (int i = 0; i < 8; ++i)
#pragma unroll
        for (int j = 0; j < 4; ++j) acc2[i][j] = 0ull;

    for (int k0 = 0; k0 < De; k0 += 10) {
#pragma unroll
        for (int i = 0; i < 5; ++i) {
            int idx = tid + i * 256, kc = idx >> 7, r = idx & 127;
            int rg = rb + r;
            As[kc][r] = (rg < Ne) ? A[(size_t)rg * De + k0 + kc] : 0.f;
        }
#pragma unroll
        for (int i = 0; i < 5; ++i) {
            int idx = tid + i * 256, kc = idx >> 7, c = idx & 127;
            Bs[kc][c] = W[(size_t)(cb + c) * 450 + doff + k0 + kc];
        }
        __syncthreads();
#pragma unroll
        for (int k = 0; k < 10; ++k) {
            float4 a0 = *reinterpret_cast<const float4*>(&As[k][tx * 4]);
            float4 a1 = *reinterpret_cast<const float4*>(&As[k][tx * 4 + 64]);
            ulonglong2 b01 = *reinterpret_cast<const ulonglong2*>(&Bs[k][ty * 4]);
            ulonglong2 b23 = *reinterpret_cast<const ulonglong2*>(&Bs[k][ty * 4 + 64]);
            float av[8] = {a0.x, a0.y, a0.z, a0.w, a1.x, a1.y, a1.z, a1.w};
#pragma unroll
            for (int i = 0; i < 8; ++i) {
                unsigned long long a2 = splat2(av[i]);
                fma2(acc2[i][0], b01.x, a2);
                fma2(acc2[i][1], b01.y, a2);
                fma2(acc2[i][2], b23.x, a2);
                fma2(acc2[i][3], b23.y, a2);
            }
        }
        __syncthreads();
    }
#pragma unroll
    for (int i = 0; i < 8; ++i) {
        int r = (i < 4) ? (tx * 4 + i) : (64 + tx * 4 + (i - 4));
        int rg = rb + r;
        if (rg >= Ne) continue;
        float o[8];
        unpk(acc2[i][0], o[0], o[1]);
        unpk(acc2[i][1], o[2], o[3]);
        unpk(acc2[i][2], o[4], o[5]);
        unpk(acc2[i][3], o[6], o[7]);
        float* dst = P + (size_t)rg * 2048 + (size_t)dir * 1024 + cb;
        *reinterpret_cast<float4*>(&dst[ty * 4]) = make_float4(o[0], o[1], o[2], o[3]);
        *reinterpret_cast<float4*>(&dst[ty * 4 + 64]) = make_float4(o[4], o[5], o[6], o[7]);
    }
}

__global__ void __launch_bounds__(256) gemm_pt_kernel(
    const float* __restrict__ Ap, const float* __restrict__ At,
    const float* __restrict__ wf, const float* __restrict__ wb)
{
    int dir = blockIdx.z;
    const float* W = dir ? wb : wf;
    if (blockIdx.x < 4)
        gemm_tile(Ap, PPY, 100, 300, W, g_Pp, blockIdx.x * 128, blockIdx.y * 128, dir);
    else
        gemm_tile(At, KK, 50, 400, W, g_Pt, 0, blockIdx.y * 128, dir);
}

// persistent BiLSTM (best-known config, R13): 128 CTAs = dir(2) x batch-tile(8) x unit-tile(8).
// Phase-1 A-fragments register-resident; h exchanged as tf32 via L2 staging.
#define SMEM_FLOATS (16 * HS + 128 * GS)

__global__ void __launch_bounds__(256, 1) lstm_kernel(
    const int* __restrict__ xi, const int* __restrict__ pin, const int* __restrict__ ptag,
    const float* __restrict__ whh_f, const float* __restrict__ whh_b,
    const float* __restrict__ bihf, const float* __restrict__ bhhf,
    const float* __restrict__ bihb, const float* __restrict__ bhhb)
{
    extern __shared__ float sm[];
    uint32_t* hs_s = reinterpret_cast<uint32_t*>(sm);   // [16][HS] tf32, batch-major
    float*    g_s  = sm + 16 * HS;                      // [128][GS] fp32

    int tid = threadIdx.x, bx = blockIdx.x;
    int dir = bx >> 6, loc = bx & 63, bi = loc >> 3, ui = loc & 7;
    const float* whh = dir ? whh_b : whh_f;
    const float* bih = dir ? bihb : bihf;
    const float* bhh = dir ? bhhb : bhhf;

    for (int i = tid; i < 16 * HS; i += 256) hs_s[i] = 0u;

    int lane = tid & 31, wp = tid >> 5;
    int gID = lane >> 2, ac = lane & 3;
    int ar = wp * 16 + gID;
    int p2_b = tid >> 5, p2_j = tid & 31;
    int u_g = ui * 32 + p2_j;
    int rb_b = tid >> 4, rcc = tid & 15;
    int rl_h0 = rcc * 16;
    bool own_chunk = ((rcc >> 1) == ui);

    uint32_t wA[128];
    {
        int rA = ar, rB = ar + 8;
        int GA = ((rA & 3) << 8) + ui * 32 + (rA >> 2);
        int GB = ((rB & 3) << 8) + ui * 32 + (rB >> 2);
        const float* wrA = whh + (size_t)GA * 256;
        const float* wrB = whh + (size_t)GB * 256;
#pragma unroll
        for (int kk = 0; kk < 32; ++kk) {
            int k = kk * 8;
            wA[4 * kk + 0] = f2tf(wrA[k + ac]);
            wA[4 * kk + 1] = f2tf(wrB[k + ac]);
            wA[4 * kk + 2] = f2tf(wrA[k + ac + 4]);
            wA[4 * kk + 3] = f2tf(wrB[k + ac + 4]);
        }
    }

    float biasr[4];
#pragma unroll
    for (int g = 0; g < 4; ++g) {
        int G = (g << 8) + u_g;
        biasr[g] = bih[G] + bhh[G];
    }
    __syncthreads();

    float cs0 = 0.f, cs1 = 0.f;
    unsigned int* barp = g_bar + (dir * 8 + bi) * 32;
    uint32_t* stg_grp = g_stg + (size_t)(dir * 8 + bi) * 2 * 16 * 256;
    int bg0 = bi * 16 + p2_b;
    int bg1 = bg0 + 8;

    for (int s = 0; s < TT; ++s) {
        int t = dir ? (TT - 1 - s) : s;

        int xv0 = xi[bg0 * TT + t], pv0 = pin[bg0 * TT + t], tv0 = ptag[bg0 * TT + t];
        int xv1 = xi[bg1 * TT + t], pv1 = pin[bg1 * TT + t], tv1 = ptag[bg1 * TT + t];
        const float* pc0 = g_Pc + (size_t)xv0 * 2048 + dir * 1024 + u_g;
        const float* pp0 = g_Pp + (size_t)pv0 * 2048 + dir * 1024 + u_g;
        const float* pt0 = g_Pt + (size_t)tv0 * 2048 + dir * 1024 + u_g;
        const float* pc1 = g_Pc + (size_t)xv1 * 2048 + dir * 1024 + u_g;
        const float* pp1 = g_Pp + (size_t)pv1 * 2048 + dir * 1024 + u_g;
        const float* pt1 = g_Pt + (size_t)tv1 * 2048 + dir * 1024 + u_g;
        float pre[2][4];
#pragma unroll
        for (int g = 0; g < 4; ++g) {
            pre[0][g] = biasr[g] + pc0[g * 256] + pp0[g * 256] + pt0[g * 256];
            pre[1][g] = biasr[g] + pc1[g * 256] + pp1[g * 256] + pt1[g * 256];
        }

        if (s > 0) {
            if (!own_chunk) {
                unsigned v, target = 8u * (unsigned)s;
                do {
                    asm volatile("ld.acquire.gpu.u32 %0, [%1];" : "=r"(v) : "l"(barp) : "memory");
                } while (v < target);
                const uint32_t* src =
                    stg_grp + (size_t)(((s - 1) & 1) * 16 + rb_b) * 256 + rl_h0;
                uint32_t* dst = hs_s + rb_b * HS + rl_h0;
#pragma unroll
                for (int q = 0; q < 4; ++q)
                    *reinterpret_cast<uint4*>(dst + q * 4) =
                        *reinterpret_cast<const uint4*>(src + q * 4);
            }
            __syncthreads();
        }

        {
            float cA[4] = {0.f, 0.f, 0.f, 0.f};
            float cB[4] = {0.f, 0.f, 0.f, 0.f};
            const uint32_t* hb0 = hs_s + gID * HS;
            const uint32_t* hb1 = hs_s + (gID + 8) * HS;
#pragma unroll
            for (int kk = 0; kk < 32; ++kk) {
                int k = kk * 8;
                uint32_t b0 = hb0[k + ac];
                uint32_t b1 = hb0[k + ac + 4];
                uint32_t b2 = hb1[k + ac];
                uint32_t b3 = hb1[k + ac + 4];
                mma_tf32(cA, wA[4 * kk], wA[4 * kk + 1], wA[4 * kk + 2], wA[4 * kk + 3], b0, b1);
                mma_tf32(cB, wA[4 * kk], wA[4 * kk + 1], wA[4 * kk + 2], wA[4 * kk + 3], b2, b3);
            }
            int bc = 2 * ac;
            g_s[ar * GS + bc]           = cA[0];
            g_s[ar * GS + bc + 1]       = cA[1];
            g_s[(ar + 8) * GS + bc]     = cA[2];
            g_s[(ar + 8) * GS + bc + 1] = cA[3];
            g_s[ar * GS + bc + 8]       = cB[0];
            g_s[ar * GS + bc + 9]       = cB[1];
            g_s[(ar + 8) * GS + bc + 8] = cB[2];
            g_s[(ar + 8) * GS + bc + 9] = cB[3];
        }
        __syncthreads();

        uint32_t* stg_w = stg_grp + (size_t)(s & 1) * 16 * 256;
#pragma unroll
        for (int cc = 0; cc < 2; ++cc) {
            int bl = p2_b + cc * 8;
            int bg = cc ? bg1 : bg0;
            float g0 = g_s[(p2_j * 4 + 0) * GS + bl];
            float g1 = g_s[(p2_j * 4 + 1) * GS + bl];
            float g2 = g_s[(p2_j * 4 + 2) * GS + bl];
            float g3 = g_s[(p2_j * 4 + 3) * GS + bl];
            float ig = sigm(pre[cc][0] + g0);
            float fg = sigm(pre[cc][1] + g1);
            float gg = tanha(pre[cc][2] + g2);
            float og = sigm(pre[cc][3] + g3);
            float c = cc ? cs1 : cs0;
            c = fg * c + ig * gg;
            if (cc) cs1 = c; else cs0 = c;
            float hv = og * tanha(c);
            uint32_t htf = f2tf(hv);
            g_h2[((size_t)(t * BB + bg)) * 512 + dir * 256 + u_g] = hv;
            stg_w[bl * 256 + u_g] = htf;
            hs_s[bl * HS + u_g] = htf;
        }
        __syncthreads();
        if (tid == 0)
            asm volatile("red.release.gpu.global.add.u32 [%0], %1;" :: "l"(barp), "r"(1u) : "memory");
    }
}

// emissions: w_out staged in smem, 64 (t,b) pairs per block
__global__ void __launch_bounds__(256) emis_kernel(
    const float* __restrict__ wout, const float* __restrict__ bout)
{
    __shared__ float ws[KK][520];
    __shared__ float bs[KK];
    int tid = threadIdx.x;
    for (int idx = tid; idx < KK * 512; idx += 256) {
        int k = idx >> 9, c = idx & 511;
        ws[k][c] = wout[idx];
    }
    if (tid < KK) bs[tid] = bout[tid];
    __syncthreads();

    int warp = tid >> 5, lane = tid & 31;
#pragma unroll
    for (int it = 0; it < 8; ++it) {
        int p = blockIdx.x * 64 + it * 8 + warp;
        const float* hr = g_h2 + (size_t)p * 512;
        float4 h[4];
#pragma unroll
        for (int c = 0; c < 4; ++c)
            h[c] = *reinterpret_cast<const float4*>(&hr[c * 128 + lane * 4]);
        float* em = g_em + (size_t)p * KK;
        for (int k = 0; k < KK; ++k) {
            float s = 0.f;
#pragma unroll
            for (int c = 0; c < 4; ++c) {
                float4 w = *reinterpret_cast<const float4*>(&ws[k][c * 128 + lane * 4]);
                s = fmaf(h[c].x, w.x, s); s = fmaf(h[c].y, w.y, s);
                s = fmaf(h[c].z, w.z, s); s = fmaf(h[c].w, w.w, s);
            }
#pragma unroll
            for (int o = 16; o; o >>= 1) s += __shfl_xor_sync(0xffffffffu, s, o);
            if (lane == 0) em[k] = s + bs[k];
        }
    }
}

// CRF NLL per batch: warp per batch, lane = tag
__global__ void __launch_bounds__(32) crf_kernel(
    const int* __restrict__ y, const float* __restrict__ start,
    const float* __restrict__ endt, const float* __restrict__ trans)
{
    int b = blockIdx.x, lane = threadIdx.x;
    bool act = lane < KK;
    float trc[KK];
#pragma unroll
    for (int j = 0; j < KK; ++j) trc[j] = act ? trans[j * KK + lane] : 0.f;

    float alpha = act ? (start[lane] + g_em[(size_t)b * KK + lane]) : -1e30f;
    for (int t = 1; t < TT; ++t) {
        float e = act ? g_em[((size_t)t * BB + b) * KK + lane] : 0.f;
        float vj[KK], m = -1e30f;
#pragma unroll
        for (int j = 0; j < KK; ++j) {
            float aj = __shfl_sync(0xffffffffu, alpha, j);
            vj[j] = aj + trc[j];
            m = fmaxf(m, vj[j]);
        }
        float ssum = 0.f;
#pragma unroll
        for (int j = 0; j < KK; ++j) ssum += __expf(vj[j] - m);
        alpha = e + m + __logf(ssum);
    }
    float v = act ? (alpha + endt[lane]) : -1e30f;
    float m = v;
#pragma unroll
    for (int o = 16; o; o >>= 1) m = fmaxf(m, __shfl_xor_sync(0xffffffffu, m, o));
    float se = act ? __expf(v - m) : 0.f;
#pragma unroll
    for (int o = 16; o; o >>= 1) se += __shfl_xor_sync(0xffffffffu, se, o);
    float logZ = m + __logf(se);

    const int* yb = y + b * TT;
    float sc = 0.f;
    for (int t = 1 + lane; t < TT; t += 32) {
        int tp = yb[t - 1], tc = yb[t];
        sc += trans[tp * KK + tc] + g_em[((size_t)t * BB + b) * KK + tc];
    }
    if (lane == 0) {
        int t0 = yb[0];
        sc += start[t0] + g_em[(size_t)b * KK + t0] + endt[yb[TT - 1]];
    }
#pragma unroll
    for (int o = 16; o; o >>= 1) sc += __shfl_xor_sync(0xffffffffu, sc, o);
    if (lane == 0) g_res[b] = sc - logZ;
}

__global__ void __launch_bounds__(32) final_kernel(float* __restrict__ out) {
    int lane = threadIdx.x;
    float s = 0.f;
    for (int i = lane; i < BB; i += 32) s += g_res[i];
#pragma unroll
    for (int o = 16; o; o >>= 1) s += __shfl_xor_sync(0xffffffffu, s, o);
    if (lane == 0) out[0] = -s;
}

extern "C" void kernel_launch(void* const* d_in, const int* in_sizes, int n_in,
                              void* d_out, int out_size) {
    const int*   x_idx   = (const int*)d_in[0];
    const int*   y_tags  = (const int*)d_in[1];
    const int*   pretag  = (const int*)d_in[2];
    const int*   pinyin  = (const int*)d_in[3];
    const float* char_emb   = (const float*)d_in[5];
    const float* tag_emb    = (const float*)d_in[6];
    const float* pinyin_emb = (const float*)d_in[7];
    const float* wihf = (const float*)d_in[8];
    const float* whhf = (const float*)d_in[9];
    const float* bihf = (const float*)d_in[10];
    const float* bhhf = (const float*)d_in[11];
    const float* wihb = (const float*)d_in[12];
    const float* whhb = (const float*)d_in[13];
    const float* bihb = (const float*)d_in[14];
    const float* bhhb = (const float*)d_in[15];
    const float* wout  = (const float*)d_in[16];
    const float* bout  = (const float*)d_in[17];
    const float* start = (const float*)d_in[18];
    const float* endt  = (const float*)d_in[19];
    const float* trans = (const float*)d_in[20];
    float* out = (float*)d_out;

    cudaFuncSetAttribute(lstm_kernel,
                         cudaFuncAttributeMaxDynamicSharedMemorySize,
                         SMEM_FLOATS * (int)sizeof(float));

    bc_init_kernel<<<1, 32>>>();
    gemm_c_mma_kernel<<<dim3(79, 16, 2), 256>>>(char_emb, wihf, wihb);
    gemm_pt_kernel<<<dim3(5, 8, 2), 256>>>(pinyin_emb, tag_emb, wihf, wihb);

    lstm_kernel<<<128, 256, SMEM_FLOATS * (int)sizeof(float)>>>(
        x_idx, pinyin, pretag, whhf, whhb, bihf, bhhf, bihb, bhhb);

    emis_kernel<<<(TT * BB) / 64, 256>>>(wout, bout);
    crf_kernel<<<BB, 32>>>(y_tags, start, endt, trans);
    final_kernel<<<1, 32>>>(out);
}